// round 14
// baseline (speedup 1.0000x reference)
#include <cuda_runtime.h>
#include <cuda_fp16.h>
#include <cstdint>

#define NN 10000
#define BB 8
#define TT 20
#define FF 9
#define MAXE 160000
#define BT (BB*TT)   // 160

// ---------------- scratch ----------------
__device__ float g_X[NN*BT];
__device__ float g_S[NN*BT];
__device__ float g_dinv[NN];
__device__ int   g_cnt[NN];
__device__ int   g_fill[NN];
__device__ int   g_row[NN];
__device__ int2  g_ev[MAXE];
__device__ int   g_is64;

__device__ __forceinline__ float tanhap(float x){
  float y; asm("tanh.approx.f32 %0, %1;" : "=f"(y) : "f"(x)); return y;
}
__device__ __forceinline__ float sigm(float x){ return fmaf(tanhap(0.5f*x), 0.5f, 0.5f); }

// ---------------- prep kernels (fused) ----------------
__global__ void k_pre(const int* __restrict__ w){
  int i = blockIdx.x*blockDim.x + threadIdx.x;
  if (i < NN){ g_cnt[i]=0; g_fill[i]=0; }
  if (blockIdx.x==0 && threadIdx.x<32){
    int v = w[2*threadIdx.x+1] | w[2*(threadIdx.x+32)+1];
    unsigned b = __ballot_sync(0xffffffffu, v==0);
    if (threadIdx.x==0) g_is64 = (b==0xffffffffu) ? 1 : 0;
  }
}
__device__ __forceinline__ int edge_at(const int* w, int is64, int idx){
  return is64 ? w[2*idx] : w[idx];
}
__global__ void k_obs_count(const float* __restrict__ obs, float* __restrict__ out,
                            const int* __restrict__ w, int E, int obsBlocks){
  if ((int)blockIdx.x < obsBlocks){
    int idx = blockIdx.x*256 + threadIdx.x;
    if (idx >= BT*NN) return;
    const float* r = obs + (size_t)idx*FF;
    float v[9];
    #pragma unroll
    for (int f=0; f<9; ++f) v[f] = r[f];
    float* o = out + (size_t)idx*72;
    *(float4*)(o)   = make_float4(v[0],v[1],v[2],v[3]);
    *(float4*)(o+4) = make_float4(v[4],v[5],v[6],v[7]);
    int bt = idx / NN, n = idx - bt*NN;
    g_X[n*BT + bt] = v[8];
  } else {
    int e = (blockIdx.x - obsBlocks)*256 + threadIdx.x;
    if (e >= E) return;
    int d = edge_at(w, g_is64, E + e);
    if ((unsigned)d < NN) atomicAdd(&g_cnt[d], 1);
  }
}
__global__ void k_scan(){
  __shared__ int sums[256];
  int tid = threadIdx.x;
  const int CH = 40;
  int base = tid*CH, s = 0;
  for (int i=0;i<CH;++i){
    int ix = base+i;
    if (ix<NN){ int c = g_cnt[ix]; s += c; g_dinv[ix] = rsqrtf((float)(c+1)); }
  }
  sums[tid]=s; __syncthreads();
  for (int off=1; off<256; off<<=1){
    int v = (tid>=off) ? sums[tid-off] : 0;
    __syncthreads();
    sums[tid] += v;
    __syncthreads();
  }
  int run = (tid>0) ? sums[tid-1] : 0;
  for (int i=0;i<CH;++i){ int ix=base+i; if (ix<NN){ g_row[ix]=run; run += g_cnt[ix]; } }
}
__global__ void k_fill(const int* __restrict__ w, int E){
  int e = blockIdx.x*blockDim.x + threadIdx.x;
  if (e >= E) return;
  int is64 = g_is64;
  int sN = edge_at(w, is64, e);
  int d  = edge_at(w, is64, E + e);
  if ((unsigned)sN >= NN || (unsigned)d >= NN) return;
  int pos = g_row[d] + atomicAdd(&g_fill[d], 1);
  g_ev[pos] = make_int2(sN, __float_as_int(g_dinv[sN]*g_dinv[d]));
}
__global__ void k_spmm(){
  int w = (blockIdx.x*blockDim.x + threadIdx.x) >> 5;
  int lane = threadIdx.x & 31;
  if (w >= NN*5) return;
  int n = w/5, c = (w - 5*n)*32 + lane;
  float dn = g_dinv[n];
  float acc = dn*dn*g_X[n*BT + c];
  int st = g_row[n], en = st + g_cnt[n];
  for (int i=st; i<en; ++i){
    int2 ev = g_ev[i];
    acc = fmaf(__int_as_float(ev.y), g_X[ev.x*BT + c], acc);
  }
  g_S[n*BT + c] = acc;
}

// ---------------- HMMA GRU (fp16 2-term, register-resident state) ----------------
__device__ __forceinline__ int qmap(int p){ return 8*(p&3) + (p>>3) + 4*((p>>2)&1); }

__device__ __forceinline__ uint32_t h2pack(float v0, float v1){
  __half2 h = __floats2half2_rn(v0, v1);
  return *(uint32_t*)&h;
}
// state pack: fp16 hi + fp16 residual (covers state to ~2^-22)
__device__ __forceinline__ void pack2h(float v0, float v1, uint32_t& ph, uint32_t& pl){
  __half2 h = __floats2half2_rn(v0, v1);
  ph = *(uint32_t*)&h;
  float r0 = v0 - __low2float(h), r1 = v1 - __high2float(h);
  __half2 l = __floats2half2_rn(r0, r1);
  pl = *(uint32_t*)&l;
}
__device__ __forceinline__ void mma16816(float d[4],
    uint32_t a0, uint32_t a1, uint32_t a2, uint32_t a3, uint32_t b0, uint32_t b1){
  asm volatile("mma.sync.aligned.m16n8k16.row.col.f32.f16.f16.f32 "
    "{%0,%1,%2,%3}, {%4,%5,%6,%7}, {%8,%9}, {%0,%1,%2,%3};"
    : "+f"(d[0]), "+f"(d[1]), "+f"(d[2]), "+f"(d[3])
    : "r"(a0), "r"(a1), "r"(a2), "r"(a3), "r"(b0), "r"(b1));
}
__device__ __forceinline__ void mma16816_z(float d[4],
    uint32_t a0, uint32_t a1, uint32_t a2, uint32_t a3, uint32_t b0, uint32_t b1){
  asm volatile("mma.sync.aligned.m16n8k16.row.col.f32.f16.f16.f32 "
    "{%0,%1,%2,%3}, {%4,%5,%6,%7}, {%8,%9}, {%10,%10,%10,%10};"
    : "=f"(d[0]), "=f"(d[1]), "=f"(d[2]), "=f"(d[3])
    : "r"(a0), "r"(a1), "r"(a2), "r"(a3), "r"(b0), "r"(b1), "f"(0.0f));
}

// SMEM offsets in 4-byte words
#define OFF_B1   0        // 128*36
#define OFF_B2   4608     // 64*36
#define OFF_S    6912     // 64*21
#define OFF_UZR  8256
#define OFF_CZR  8384
#define OFF_UH   8512
#define OFF_CH   8576
#define SM_WORDS 8640     // 34560 bytes

// one 8-nchunk matvec pass, 2 MMAs per (n,kt); acc zeroed via zero-C first MMA
__device__ __forceinline__ void mv_pass(const uint32_t* __restrict__ B,
                                        const uint32_t* Ah, const uint32_t* Al,
                                        float acc[8][4], int g, int tig, int nchBase){
  #pragma unroll
  for (int n=0;n<8;++n){
    const uint32_t* bp = B + (8*(nchBase+n)+g)*36 + 8*tig;
    uint4 b0 = *(const uint4*)bp;
    uint4 b1 = *(const uint4*)(bp+4);
    const uint32_t* b0p = (const uint32_t*)&b0;
    const uint32_t* b1p = (const uint32_t*)&b1;
    mma16816_z(acc[n], Ah[0], Ah[1], Ah[2], Ah[3], b0p[0], b1p[0]);
    mma16816 (acc[n], Al[0], Al[1], Al[2], Al[3], b0p[0], b1p[0]);
    #pragma unroll
    for (int kt=1;kt<4;++kt){
      mma16816(acc[n], Ah[4*kt], Ah[4*kt+1], Ah[4*kt+2], Ah[4*kt+3], b0p[kt], b1p[kt]);
      mma16816(acc[n], Al[4*kt], Al[4*kt+1], Al[4*kt+2], Al[4*kt+3], b0p[kt], b1p[kt]);
    }
  }
}

__global__ void __launch_bounds__(128,3) k_hmma(
   const float* __restrict__ Wcz, const float* __restrict__ bcz,
   const float* __restrict__ Wlz, const float* __restrict__ blz,
   const float* __restrict__ Wcr, const float* __restrict__ bcr,
   const float* __restrict__ Wlr, const float* __restrict__ blr,
   const float* __restrict__ Wch, const float* __restrict__ bch,
   const float* __restrict__ Wlh, const float* __restrict__ blh,
   float* __restrict__ out)
{
  extern __shared__ __align__(16) uint32_t sm[];
  float* smf = (float*)sm;

  int tid = threadIdx.x, lane = tid & 31, w = tid >> 5;
  int g = lane >> 2, tig = lane & 3;

  // ---- prologue: weights -> single fp16 fragment layout ----
  for (int idx = tid; idx < 128*32; idx += 128){
    int n = idx >> 5, p = idx & 31;
    int k0 = 2*p;
    float w0, w1;
    if (n < 64){ w0 = Wlz[(64+k0)*64 + n];  w1 = Wlz[(65+k0)*64 + n]; }
    else       { w0 = Wlr[(64+k0)*64 + n-64]; w1 = Wlr[(65+k0)*64 + n-64]; }
    sm[OFF_B1 + n*36 + qmap(p)] = h2pack(w0, w1);
  }
  for (int idx = tid; idx < 64*32; idx += 128){
    int n = idx >> 5, p = idx & 31;
    int k0 = 2*p;
    sm[OFF_B2 + n*36 + qmap(p)] = h2pack(Wlh[(64+k0)*64 + n], Wlh[(65+k0)*64 + n]);
  }
  for (int jj = tid; jj < 192; jj += 128){
    if (jj < 128){
      int j = jj & 63;
      const float* W  = (jj<64) ? Wlz : Wlr;
      const float* Wc = (jj<64) ? Wcz : Wcr;
      const float* bc = (jj<64) ? bcz : bcr;
      const float* bl = (jj<64) ? blz : blr;
      float u = 0.f, cc = 0.f;
      for (int k=0;k<64;++k){ float ww = W[k*64+j]; u = fmaf(Wc[k], ww, u); cc = fmaf(bc[k], ww, cc); }
      smf[OFF_UZR + jj] = u; smf[OFF_CZR + jj] = cc + bl[j];
    } else {
      int j = jj - 128;
      float u = 0.f, cc = 0.f;
      for (int k=0;k<64;++k){ float ww = Wlh[k*64+j]; u = fmaf(Wch[k], ww, u); cc = fmaf(bch[k], ww, cc); }
      smf[OFF_UH + j] = u; smf[OFF_CH + j] = cc + blh[j];
    }
  }
  int pbase = blockIdx.x*64;
  for (int idx = tid; idx < 64*20; idx += 128){
    int r = idx/20, t = idx - 20*r;
    int p = pbase + r; int b = p/NN, n = p - b*NN;
    smf[OFF_S + r*21 + t] = g_S[n*BT + b*TT + t];
  }
  __syncthreads();

  // warp-local rows
  int r0 = 16*w + g, r1 = r0 + 8;
  int P0 = pbase + r0, P1 = pbase + r1;
  int b0 = P0/NN, n0 = P0 - b0*NN;
  int b1 = P1/NN, n1 = P1 - b1*NN;
  float* out0 = out + ((size_t)(b0*TT)*NN + n0)*72 + 8 + 2*tig;
  float* out1 = out + ((size_t)(b1*TT)*NN + n1)*72 + 8 + 2*tig;
  const float* S0 = smf + OFF_S + r0*21;
  const float* S1 = smf + OFF_S + r1*21;

  const float2* uzr2 = (const float2*)(smf + OFF_UZR);
  const float2* czr2 = (const float2*)(smf + OFF_CZR);
  const float2* uh22 = (const float2*)(smf + OFF_UH);
  const float2* ch22 = (const float2*)(smf + OFF_CH);

  float h[8][4];
  uint32_t Ah[16], Al[16];

  // ---- t = 0: H = 0, closed form ----
  {
    float s0 = S0[0], s1 = S1[0];
    #pragma unroll
    for (int n=0;n<8;++n){
      float2 uz = uzr2[4*n+tig], cz = czr2[4*n+tig];
      float2 uh = uh22[4*n+tig], ch = ch22[4*n+tig];
      #pragma unroll
      for (int j=0;j<4;++j){
        float s = (j<2) ? s0 : s1;
        float u  = (j&1) ? uz.y : uz.x;
        float c  = (j&1) ? cz.y : cz.x;
        float uu = (j&1) ? uh.y : uh.x;
        float cc = (j&1) ? ch.y : ch.x;
        float z  = sigm(fmaf(s, u, c));
        float ht = tanhap(fmaf(s, uu, cc));
        h[n][j] = (1.f - z)*ht;
      }
      *(float2*)(out0 + 8*n) = make_float2(h[n][0], h[n][1]);
      *(float2*)(out1 + 8*n) = make_float2(h[n][2], h[n][3]);
      int kt = n>>1, half = n&1;
      pack2h(h[n][0], h[n][1], Ah[4*kt+2*half],   Al[4*kt+2*half]);
      pack2h(h[n][2], h[n][3], Ah[4*kt+2*half+1], Al[4*kt+2*half+1]);
    }
    out0 += (size_t)NN*72;
    out1 += (size_t)NN*72;
  }

  for (int t=1; t<TT; ++t){
    float s0 = S0[t], s1 = S1[t];
    float acc[8][4];

    // ---- pass 1a: z (cols 0..63) ----
    mv_pass(sm + OFF_B1, Ah, Al, acc, g, tig, 0);
    float z[8][4];
    #pragma unroll
    for (int n=0;n<8;++n){
      float2 uz = uzr2[4*n+tig], cz = czr2[4*n+tig];
      #pragma unroll
      for (int j=0;j<4;++j){
        float s = (j<2) ? s0 : s1;
        float u = (j&1) ? uz.y : uz.x;
        float c = (j&1) ? cz.y : cz.x;
        z[n][j] = sigm(acc[n][j] + fmaf(s, u, c));
      }
    }

    // ---- pass 1b: r (cols 64..127) -> HR packed straight into A frags ----
    mv_pass(sm + OFF_B1, Ah, Al, acc, g, tig, 8);
    #pragma unroll
    for (int n=0;n<8;++n){
      float2 uz = uzr2[32 + 4*n+tig], cz = czr2[32 + 4*n+tig];
      float hr[4];
      #pragma unroll
      for (int j=0;j<4;++j){
        float s = (j<2) ? s0 : s1;
        float u = (j&1) ? uz.y : uz.x;
        float c = (j&1) ? cz.y : cz.x;
        float r = sigm(acc[n][j] + fmaf(s, u, c));
        hr[j] = h[n][j] * r;
      }
      int kt = n>>1, half = n&1;
      pack2h(hr[0], hr[1], Ah[4*kt+2*half],   Al[4*kt+2*half]);
      pack2h(hr[2], hr[3], Ah[4*kt+2*half+1], Al[4*kt+2*half+1]);
    }

    // ---- pass 2: htil = HR . Uh; blend; out; repack H ----
    mv_pass(sm + OFF_B2, Ah, Al, acc, g, tig, 0);
    #pragma unroll
    for (int n=0;n<8;++n){
      float2 uh = uh22[4*n+tig], ch = ch22[4*n+tig];
      #pragma unroll
      for (int j=0;j<4;++j){
        float s = (j<2) ? s0 : s1;
        float u = (j&1) ? uh.y : uh.x;
        float c = (j&1) ? ch.y : ch.x;
        float ht = tanhap(acc[n][j] + fmaf(s, u, c));
        h[n][j] = fmaf(z[n][j], h[n][j] - ht, ht);
      }
      *(float2*)(out0 + 8*n) = make_float2(h[n][0], h[n][1]);
      *(float2*)(out1 + 8*n) = make_float2(h[n][2], h[n][3]);
      int kt = n>>1, half = n&1;
      pack2h(h[n][0], h[n][1], Ah[4*kt+2*half],   Al[4*kt+2*half]);
      pack2h(h[n][2], h[n][3], Ah[4*kt+2*half+1], Al[4*kt+2*half+1]);
    }
    out0 += (size_t)NN*72;
    out1 += (size_t)NN*72;
  }
}

extern "C" void kernel_launch(void* const* d_in, const int* in_sizes, int n_in,
                              void* d_out, int out_size) {
  const float* obs = (const float*)d_in[0];
  const int* ei32 = (const int*)d_in[1];
  int E = in_sizes[1] / 2;
  if (E > MAXE) E = MAXE;
  float* out = (float*)d_out;

  const int SMB = SM_WORDS*4;   // 34560 B
  cudaFuncSetAttribute(k_hmma, cudaFuncAttributeMaxDynamicSharedMemorySize, SMB);

  int obsBlocks = (BT*NN+255)/256;
  int cntBlocks = (E+255)/256;
  k_pre<<<(NN+255)/256, 256>>>(ei32);
  k_obs_count<<<obsBlocks+cntBlocks, 256>>>(obs, out, ei32, E, obsBlocks);
  k_scan<<<1, 256>>>();
  k_fill<<<cntBlocks, 256>>>(ei32, E);
  k_spmm<<<(NN*5*32+255)/256, 256>>>();
  k_hmma<<<(BB*NN)/64, 128, SMB>>>(
    (const float*)d_in[2], (const float*)d_in[3], (const float*)d_in[4], (const float*)d_in[5],
    (const float*)d_in[6], (const float*)d_in[7], (const float*)d_in[8], (const float*)d_in[9],
    (const float*)d_in[10], (const float*)d_in[11], (const float*)d_in[12], (const float*)d_in[13],
    out);
}

// round 15
// speedup vs baseline: 1.4736x; 1.4736x over previous
#include <cuda_runtime.h>
#include <cuda_bf16.h>
#include <cstdint>

#define NN 10000
#define BB 8
#define TT 20
#define FF 9
#define MAXE 160000
#define BT (BB*TT)   // 160

// ---------------- scratch ----------------
__device__ float g_X[NN*BT];
__device__ float g_S[NN*BT];
__device__ float g_dinv[NN];
__device__ int   g_cnt[NN];
__device__ int   g_fill[NN];
__device__ int   g_row[NN];
__device__ int2  g_ev[MAXE];
__device__ int   g_is64;

__device__ __forceinline__ float tanhap(float x){
  float y; asm("tanh.approx.f32 %0, %1;" : "=f"(y) : "f"(x)); return y;
}
__device__ __forceinline__ float sigm(float x){ return fmaf(tanhap(0.5f*x), 0.5f, 0.5f); }

// ---------------- prep kernels (fused) ----------------
__global__ void k_pre(const int* __restrict__ w){
  int i = blockIdx.x*blockDim.x + threadIdx.x;
  if (i < NN){ g_cnt[i]=0; g_fill[i]=0; }
  if (blockIdx.x==0 && threadIdx.x<32){
    int v = w[2*threadIdx.x+1] | w[2*(threadIdx.x+32)+1];
    unsigned b = __ballot_sync(0xffffffffu, v==0);
    if (threadIdx.x==0) g_is64 = (b==0xffffffffu) ? 1 : 0;
  }
}
__device__ __forceinline__ int edge_at(const int* w, int is64, int idx){
  return is64 ? w[2*idx] : w[idx];
}
__global__ void k_obs_count(const float* __restrict__ obs, float* __restrict__ out,
                            const int* __restrict__ w, int E, int obsBlocks){
  if ((int)blockIdx.x < obsBlocks){
    int idx = blockIdx.x*256 + threadIdx.x;
    if (idx >= BT*NN) return;
    const float* r = obs + (size_t)idx*FF;
    float v[9];
    #pragma unroll
    for (int f=0; f<9; ++f) v[f] = r[f];
    float* o = out + (size_t)idx*72;
    *(float4*)(o)   = make_float4(v[0],v[1],v[2],v[3]);
    *(float4*)(o+4) = make_float4(v[4],v[5],v[6],v[7]);
    int bt = idx / NN, n = idx - bt*NN;
    g_X[n*BT + bt] = v[8];
  } else {
    int e = (blockIdx.x - obsBlocks)*256 + threadIdx.x;
    if (e >= E) return;
    int d = edge_at(w, g_is64, E + e);
    if ((unsigned)d < NN) atomicAdd(&g_cnt[d], 1);
  }
}
__global__ void k_scan(){
  __shared__ int sums[256];
  int tid = threadIdx.x;
  const int CH = 40;
  int base = tid*CH, s = 0;
  for (int i=0;i<CH;++i){
    int ix = base+i;
    if (ix<NN){ int c = g_cnt[ix]; s += c; g_dinv[ix] = rsqrtf((float)(c+1)); }
  }
  sums[tid]=s; __syncthreads();
  for (int off=1; off<256; off<<=1){
    int v = (tid>=off) ? sums[tid-off] : 0;
    __syncthreads();
    sums[tid] += v;
    __syncthreads();
  }
  int run = (tid>0) ? sums[tid-1] : 0;
  for (int i=0;i<CH;++i){ int ix=base+i; if (ix<NN){ g_row[ix]=run; run += g_cnt[ix]; } }
}
__global__ void k_fill(const int* __restrict__ w, int E){
  int e = blockIdx.x*blockDim.x + threadIdx.x;
  if (e >= E) return;
  int is64 = g_is64;
  int sN = edge_at(w, is64, e);
  int d  = edge_at(w, is64, E + e);
  if ((unsigned)sN >= NN || (unsigned)d >= NN) return;
  int pos = g_row[d] + atomicAdd(&g_fill[d], 1);
  g_ev[pos] = make_int2(sN, __float_as_int(g_dinv[sN]*g_dinv[d]));
}
__global__ void k_spmm(){
  int w = (blockIdx.x*blockDim.x + threadIdx.x) >> 5;
  int lane = threadIdx.x & 31;
  if (w >= NN*5) return;
  int n = w/5, c = (w - 5*n)*32 + lane;
  float dn = g_dinv[n];
  float acc = dn*dn*g_X[n*BT + c];
  int st = g_row[n], en = st + g_cnt[n];
  for (int i=st; i<en; ++i){
    int2 ev = g_ev[i];
    acc = fmaf(__int_as_float(ev.y), g_X[ev.x*BT + c], acc);
  }
  g_S[n*BT + c] = acc;
}

// ---------------- HMMA GRU (bf16 2-term, register-resident state) ----------------
__device__ __forceinline__ int qmap(int p){ return 8*(p&3) + (p>>3) + 4*((p>>2)&1); }

__device__ __forceinline__ uint32_t bf2pack(float lo_elem, float hi_elem){
  uint32_t r;
  asm("cvt.rn.bf16x2.f32 %0, %1, %2;" : "=r"(r) : "f"(hi_elem), "f"(lo_elem));
  return r;
}
__device__ __forceinline__ float bfhi(float x){
  return __bfloat162float(__float2bfloat16(x));
}
// state pack: bf16 hi + bf16 residual, hi recovered via bit ops (no F2F)
__device__ __forceinline__ void pack2(float v0, float v1, uint32_t& ph, uint32_t& pl){
  ph = bf2pack(v0, v1);
  float h0 = __uint_as_float(ph << 16);
  float h1 = __uint_as_float(ph & 0xFFFF0000u);
  pl = bf2pack(v0 - h0, v1 - h1);
}
__device__ __forceinline__ void mma16816(float d[4],
    uint32_t a0, uint32_t a1, uint32_t a2, uint32_t a3, uint32_t b0, uint32_t b1){
  asm volatile("mma.sync.aligned.m16n8k16.row.col.f32.bf16.bf16.f32 "
    "{%0,%1,%2,%3}, {%4,%5,%6,%7}, {%8,%9}, {%0,%1,%2,%3};"
    : "+f"(d[0]), "+f"(d[1]), "+f"(d[2]), "+f"(d[3])
    : "r"(a0), "r"(a1), "r"(a2), "r"(a3), "r"(b0), "r"(b1));
}
__device__ __forceinline__ void mma16816_z(float d[4],
    uint32_t a0, uint32_t a1, uint32_t a2, uint32_t a3, uint32_t b0, uint32_t b1){
  asm volatile("mma.sync.aligned.m16n8k16.row.col.f32.bf16.bf16.f32 "
    "{%0,%1,%2,%3}, {%4,%5,%6,%7}, {%8,%9}, {%10,%10,%10,%10};"
    : "=f"(d[0]), "=f"(d[1]), "=f"(d[2]), "=f"(d[3])
    : "r"(a0), "r"(a1), "r"(a2), "r"(a3), "r"(b0), "r"(b1), "f"(0.0f));
}

// SMEM offsets in 4-byte words
#define OFF_B1   0        // 128*36
#define OFF_B2   4608     // 64*36
#define OFF_S    6912     // 64*21
#define OFF_UZR  8256
#define OFF_CZR  8384
#define OFF_UH   8512
#define OFF_CH   8576
#define SM_WORDS 8640     // 34560 bytes

// one 8-nchunk matvec pass, 2 MMAs per (n,kt): Ahi.B + Alo.B
__device__ __forceinline__ void mv_pass(const uint32_t* __restrict__ B,
                                        const uint32_t* Ah, const uint32_t* Al,
                                        float acc[8][4], int g, int tig, int nchBase){
  #pragma unroll
  for (int n=0;n<8;++n){
    const uint32_t* bp = B + (8*(nchBase+n)+g)*36 + 8*tig;
    uint4 b0 = *(const uint4*)bp;
    uint4 b1 = *(const uint4*)(bp+4);
    const uint32_t* b0p = (const uint32_t*)&b0;
    const uint32_t* b1p = (const uint32_t*)&b1;
    mma16816_z(acc[n], Ah[0], Ah[1], Ah[2], Ah[3], b0p[0], b1p[0]);
    mma16816 (acc[n], Al[0], Al[1], Al[2], Al[3], b0p[0], b1p[0]);
    #pragma unroll
    for (int kt=1;kt<4;++kt){
      mma16816(acc[n], Ah[4*kt], Ah[4*kt+1], Ah[4*kt+2], Ah[4*kt+3], b0p[kt], b1p[kt]);
      mma16816(acc[n], Al[4*kt], Al[4*kt+1], Al[4*kt+2], Al[4*kt+3], b0p[kt], b1p[kt]);
    }
  }
}

__global__ void __launch_bounds__(128,3) k_hmma(
   const float* __restrict__ Wcz, const float* __restrict__ bcz,
   const float* __restrict__ Wlz, const float* __restrict__ blz,
   const float* __restrict__ Wcr, const float* __restrict__ bcr,
   const float* __restrict__ Wlr, const float* __restrict__ blr,
   const float* __restrict__ Wch, const float* __restrict__ bch,
   const float* __restrict__ Wlh, const float* __restrict__ blh,
   float* __restrict__ out)
{
  extern __shared__ __align__(16) uint32_t sm[];
  float* smf = (float*)sm;

  int tid = threadIdx.x, lane = tid & 31, w = tid >> 5;
  int g = lane >> 2, tig = lane & 3;

  // ---- prologue: weights -> single bf16 fragment layout ----
  for (int idx = tid; idx < 128*32; idx += 128){
    int n = idx >> 5, p = idx & 31;
    int k0 = 2*p;
    float w0, w1;
    if (n < 64){ w0 = Wlz[(64+k0)*64 + n];  w1 = Wlz[(65+k0)*64 + n]; }
    else       { w0 = Wlr[(64+k0)*64 + n-64]; w1 = Wlr[(65+k0)*64 + n-64]; }
    sm[OFF_B1 + n*36 + qmap(p)] = bf2pack(w0, w1);
  }
  for (int idx = tid; idx < 64*32; idx += 128){
    int n = idx >> 5, p = idx & 31;
    int k0 = 2*p;
    sm[OFF_B2 + n*36 + qmap(p)] = bf2pack(Wlh[(64+k0)*64 + n], Wlh[(65+k0)*64 + n]);
  }
  for (int jj = tid; jj < 192; jj += 128){
    if (jj < 128){
      int j = jj & 63;
      const float* W  = (jj<64) ? Wlz : Wlr;
      const float* Wc = (jj<64) ? Wcz : Wcr;
      const float* bc = (jj<64) ? bcz : bcr;
      const float* bl = (jj<64) ? blz : blr;
      float u = 0.f, cc = 0.f;
      for (int k=0;k<64;++k){ float ww = W[k*64+j]; u = fmaf(Wc[k], ww, u); cc = fmaf(bc[k], ww, cc); }
      smf[OFF_UZR + jj] = u; smf[OFF_CZR + jj] = cc + bl[j];
    } else {
      int j = jj - 128;
      float u = 0.f, cc = 0.f;
      for (int k=0;k<64;++k){ float ww = Wlh[k*64+j]; u = fmaf(Wch[k], ww, u); cc = fmaf(bch[k], ww, cc); }
      smf[OFF_UH + j] = u; smf[OFF_CH + j] = cc + blh[j];
    }
  }
  int pbase = blockIdx.x*64;
  for (int idx = tid; idx < 64*20; idx += 128){
    int r = idx/20, t = idx - 20*r;
    int p = pbase + r; int b = p/NN, n = p - b*NN;
    smf[OFF_S + r*21 + t] = g_S[n*BT + b*TT + t];
  }
  __syncthreads();

  // warp-local rows
  int r0 = 16*w + g, r1 = r0 + 8;
  int P0 = pbase + r0, P1 = pbase + r1;
  int b0 = P0/NN, n0 = P0 - b0*NN;
  int b1 = P1/NN, n1 = P1 - b1*NN;
  float* out0 = out + ((size_t)(b0*TT)*NN + n0)*72 + 8 + 2*tig;
  float* out1 = out + ((size_t)(b1*TT)*NN + n1)*72 + 8 + 2*tig;
  const float* S0 = smf + OFF_S + r0*21;
  const float* S1 = smf + OFF_S + r1*21;

  const float2* uzr2 = (const float2*)(smf + OFF_UZR);
  const float2* czr2 = (const float2*)(smf + OFF_CZR);
  const float2* uh22 = (const float2*)(smf + OFF_UH);
  const float2* ch22 = (const float2*)(smf + OFF_CH);

  float h[8][4];
  uint32_t Ah[16], Al[16];

  // ---- t = 0: H = 0, closed form ----
  {
    float s0 = S0[0], s1 = S1[0];
    #pragma unroll
    for (int n=0;n<8;++n){
      float2 uz = uzr2[4*n+tig], cz = czr2[4*n+tig];
      float2 uh = uh22[4*n+tig], ch = ch22[4*n+tig];
      #pragma unroll
      for (int j=0;j<4;++j){
        float s = (j<2) ? s0 : s1;
        float u  = (j&1) ? uz.y : uz.x;
        float c  = (j&1) ? cz.y : cz.x;
        float uu = (j&1) ? uh.y : uh.x;
        float cc = (j&1) ? ch.y : ch.x;
        float z  = sigm(fmaf(s, u, c));
        float ht = tanhap(fmaf(s, uu, cc));
        h[n][j] = (1.f - z)*ht;
      }
      *(float2*)(out0 + 8*n) = make_float2(h[n][0], h[n][1]);
      *(float2*)(out1 + 8*n) = make_float2(h[n][2], h[n][3]);
      int kt = n>>1, half = n&1;
      pack2(h[n][0], h[n][1], Ah[4*kt+2*half],   Al[4*kt+2*half]);
      pack2(h[n][2], h[n][3], Ah[4*kt+2*half+1], Al[4*kt+2*half+1]);
    }
    out0 += (size_t)NN*72;
    out1 += (size_t)NN*72;
  }

  for (int t=1; t<TT; ++t){
    float s0 = S0[t], s1 = S1[t];
    float acc[8][4];

    // ---- pass 1a: z (cols 0..63) ----
    mv_pass(sm + OFF_B1, Ah, Al, acc, g, tig, 0);
    float z[8][4];
    #pragma unroll
    for (int n=0;n<8;++n){
      float2 uz = uzr2[4*n+tig], cz = czr2[4*n+tig];
      #pragma unroll
      for (int j=0;j<4;++j){
        float s = (j<2) ? s0 : s1;
        float u = (j&1) ? uz.y : uz.x;
        float c = (j&1) ? cz.y : cz.x;
        z[n][j] = sigm(acc[n][j] + fmaf(s, u, c));
      }
    }

    // ---- pass 1b: r (cols 64..127) -> HR packed straight into A frags ----
    mv_pass(sm + OFF_B1, Ah, Al, acc, g, tig, 8);
    #pragma unroll
    for (int n=0;n<8;++n){
      float2 uz = uzr2[32 + 4*n+tig], cz = czr2[32 + 4*n+tig];
      float hr[4];
      #pragma unroll
      for (int j=0;j<4;++j){
        float s = (j<2) ? s0 : s1;
        float u = (j&1) ? uz.y : uz.x;
        float c = (j&1) ? cz.y : cz.x;
        float r = sigm(acc[n][j] + fmaf(s, u, c));
        hr[j] = h[n][j] * r;
      }
      int kt = n>>1, half = n&1;
      pack2(hr[0], hr[1], Ah[4*kt+2*half],   Al[4*kt+2*half]);
      pack2(hr[2], hr[3], Ah[4*kt+2*half+1], Al[4*kt+2*half+1]);
    }

    // ---- pass 2: htil = HR . Uh; blend; out; repack H ----
    mv_pass(sm + OFF_B2, Ah, Al, acc, g, tig, 0);
    #pragma unroll
    for (int n=0;n<8;++n){
      float2 uh = uh22[4*n+tig], ch = ch22[4*n+tig];
      #pragma unroll
      for (int j=0;j<4;++j){
        float s = (j<2) ? s0 : s1;
        float u = (j&1) ? uh.y : uh.x;
        float c = (j&1) ? ch.y : ch.x;
        float ht = tanhap(acc[n][j] + fmaf(s, u, c));
        h[n][j] = fmaf(z[n][j], h[n][j] - ht, ht);
      }
      *(float2*)(out0 + 8*n) = make_float2(h[n][0], h[n][1]);
      *(float2*)(out1 + 8*n) = make_float2(h[n][2], h[n][3]);
      int kt = n>>1, half = n&1;
      pack2(h[n][0], h[n][1], Ah[4*kt+2*half],   Al[4*kt+2*half]);
      pack2(h[n][2], h[n][3], Ah[4*kt+2*half+1], Al[4*kt+2*half+1]);
    }
    out0 += (size_t)NN*72;
    out1 += (size_t)NN*72;
  }
}

extern "C" void kernel_launch(void* const* d_in, const int* in_sizes, int n_in,
                              void* d_out, int out_size) {
  const float* obs = (const float*)d_in[0];
  const int* ei32 = (const int*)d_in[1];
  int E = in_sizes[1] / 2;
  if (E > MAXE) E = MAXE;
  float* out = (float*)d_out;

  const int SMB = SM_WORDS*4;   // 34560 B
  cudaFuncSetAttribute(k_hmma, cudaFuncAttributeMaxDynamicSharedMemorySize, SMB);

  int obsBlocks = (BT*NN+255)/256;
  int cntBlocks = (E+255)/256;
  k_pre<<<(NN+255)/256, 256>>>(ei32);
  k_obs_count<<<obsBlocks+cntBlocks, 256>>>(obs, out, ei32, E, obsBlocks);
  k_scan<<<1, 256>>>();
  k_fill<<<cntBlocks, 256>>>(ei32, E);
  k_spmm<<<(NN*5*32+255)/256, 256>>>();
  k_hmma<<<(BB*NN)/64, 128, SMB>>>(
    (const float*)d_in[2], (const float*)d_in[3], (const float*)d_in[4], (const float*)d_in[5],
    (const float*)d_in[6], (const float*)d_in[7], (const float*)d_in[8], (const float*)d_in[9],
    (const float*)d_in[10], (const float*)d_in[11], (const float*)d_in[12], (const float*)d_in[13],
    out);
}

// round 16
// speedup vs baseline: 1.8318x; 1.2431x over previous
#include <cuda_runtime.h>
#include <cuda_bf16.h>
#include <cstdint>

#define NN 10000
#define BB 8
#define TT 20
#define FF 9
#define MAXE 160000
#define BT (BB*TT)   // 160

// ---------------- scratch ----------------
__device__ float g_X[NN*BT];
__device__ float g_S[NN*BT];
__device__ float g_dinv[NN];
__device__ int   g_cnt[NN];
__device__ int   g_fill[NN];
__device__ int   g_row[NN];
__device__ int2  g_ev[MAXE];
__device__ int   g_is64;

__device__ __forceinline__ float tanhap(float x){
  float y; asm("tanh.approx.f32 %0, %1;" : "=f"(y) : "f"(x)); return y;
}
__device__ __forceinline__ float sigm(float x){ return fmaf(tanhap(0.5f*x), 0.5f, 0.5f); }

// ---------------- prep kernels (fused) ----------------
__global__ void k_pre(const int* __restrict__ w){
  int i = blockIdx.x*blockDim.x + threadIdx.x;
  if (i < NN){ g_cnt[i]=0; g_fill[i]=0; }
  if (blockIdx.x==0 && threadIdx.x<32){
    int v = w[2*threadIdx.x+1] | w[2*(threadIdx.x+32)+1];
    unsigned b = __ballot_sync(0xffffffffu, v==0);
    if (threadIdx.x==0) g_is64 = (b==0xffffffffu) ? 1 : 0;
  }
}
__device__ __forceinline__ int edge_at(const int* w, int is64, int idx){
  return is64 ? w[2*idx] : w[idx];
}
__global__ void k_obs_count(const float* __restrict__ obs, float* __restrict__ out,
                            const int* __restrict__ w, int E, int obsBlocks){
  if ((int)blockIdx.x < obsBlocks){
    int idx = blockIdx.x*256 + threadIdx.x;
    if (idx >= BT*NN) return;
    const float* r = obs + (size_t)idx*FF;
    float v[9];
    #pragma unroll
    for (int f=0; f<9; ++f) v[f] = r[f];
    float* o = out + (size_t)idx*72;
    *(float4*)(o)   = make_float4(v[0],v[1],v[2],v[3]);
    *(float4*)(o+4) = make_float4(v[4],v[5],v[6],v[7]);
    int bt = idx / NN, n = idx - bt*NN;
    g_X[n*BT + bt] = v[8];
  } else {
    int e = (blockIdx.x - obsBlocks)*256 + threadIdx.x;
    if (e >= E) return;
    int d = edge_at(w, g_is64, E + e);
    if ((unsigned)d < NN) atomicAdd(&g_cnt[d], 1);
  }
}
__global__ void k_scan(){
  __shared__ int sums[256];
  int tid = threadIdx.x;
  const int CH = 40;
  int base = tid*CH, s = 0;
  for (int i=0;i<CH;++i){
    int ix = base+i;
    if (ix<NN){ int c = g_cnt[ix]; s += c; g_dinv[ix] = rsqrtf((float)(c+1)); }
  }
  sums[tid]=s; __syncthreads();
  for (int off=1; off<256; off<<=1){
    int v = (tid>=off) ? sums[tid-off] : 0;
    __syncthreads();
    sums[tid] += v;
    __syncthreads();
  }
  int run = (tid>0) ? sums[tid-1] : 0;
  for (int i=0;i<CH;++i){ int ix=base+i; if (ix<NN){ g_row[ix]=run; run += g_cnt[ix]; } }
}
__global__ void k_fill(const int* __restrict__ w, int E){
  int e = blockIdx.x*blockDim.x + threadIdx.x;
  if (e >= E) return;
  int is64 = g_is64;
  int sN = edge_at(w, is64, e);
  int d  = edge_at(w, is64, E + e);
  if ((unsigned)sN >= NN || (unsigned)d >= NN) return;
  int pos = g_row[d] + atomicAdd(&g_fill[d], 1);
  g_ev[pos] = make_int2(sN, __float_as_int(g_dinv[sN]*g_dinv[d]));
}
__global__ void k_spmm(){
  int w = (blockIdx.x*blockDim.x + threadIdx.x) >> 5;
  int lane = threadIdx.x & 31;
  if (w >= NN*5) return;
  int n = w/5, c = (w - 5*n)*32 + lane;
  float dn = g_dinv[n];
  float acc = dn*dn*g_X[n*BT + c];
  int st = g_row[n], en = st + g_cnt[n];
  for (int i=st; i<en; ++i){
    int2 ev = g_ev[i];
    acc = fmaf(__int_as_float(ev.y), g_X[ev.x*BT + c], acc);
  }
  g_S[n*BT + c] = acc;
}

// ---------------- HMMA GRU (bf16 1-term, register-resident state) ----------------
__device__ __forceinline__ int qmap(int p){ return 8*(p&3) + (p>>3) + 4*((p>>2)&1); }

__device__ __forceinline__ uint32_t bf2pack(float lo_elem, float hi_elem){
  uint32_t r;
  asm("cvt.rn.bf16x2.f32 %0, %1, %2;" : "=r"(r) : "f"(hi_elem), "f"(lo_elem));
  return r;
}
__device__ __forceinline__ void mma16816(float d[4],
    uint32_t a0, uint32_t a1, uint32_t a2, uint32_t a3, uint32_t b0, uint32_t b1){
  asm volatile("mma.sync.aligned.m16n8k16.row.col.f32.bf16.bf16.f32 "
    "{%0,%1,%2,%3}, {%4,%5,%6,%7}, {%8,%9}, {%0,%1,%2,%3};"
    : "+f"(d[0]), "+f"(d[1]), "+f"(d[2]), "+f"(d[3])
    : "r"(a0), "r"(a1), "r"(a2), "r"(a3), "r"(b0), "r"(b1));
}
__device__ __forceinline__ void mma16816_z(float d[4],
    uint32_t a0, uint32_t a1, uint32_t a2, uint32_t a3, uint32_t b0, uint32_t b1){
  asm volatile("mma.sync.aligned.m16n8k16.row.col.f32.bf16.bf16.f32 "
    "{%0,%1,%2,%3}, {%4,%5,%6,%7}, {%8,%9}, {%10,%10,%10,%10};"
    : "=f"(d[0]), "=f"(d[1]), "=f"(d[2]), "=f"(d[3])
    : "r"(a0), "r"(a1), "r"(a2), "r"(a3), "r"(b0), "r"(b1), "f"(0.0f));
}

// SMEM offsets in 4-byte words
#define OFF_B1   0        // 128*36
#define OFF_B2   4608     // 64*36
#define OFF_S    6912     // 64*21
#define OFF_UZR  8256
#define OFF_CZR  8384
#define OFF_UH   8512
#define OFF_CH   8576
#define SM_WORDS 8640     // 34560 bytes

// one 8-nchunk matvec pass, 1 MMA per (n,kt): A.B with bf16 state/weights
__device__ __forceinline__ void mv_pass(const uint32_t* __restrict__ B,
                                        const uint32_t* Ah,
                                        float acc[8][4], int g, int tig, int nchBase){
  #pragma unroll
  for (int n=0;n<8;++n){
    const uint32_t* bp = B + (8*(nchBase+n)+g)*36 + 8*tig;
    uint4 b0 = *(const uint4*)bp;
    uint4 b1 = *(const uint4*)(bp+4);
    const uint32_t* b0p = (const uint32_t*)&b0;
    const uint32_t* b1p = (const uint32_t*)&b1;
    mma16816_z(acc[n], Ah[0], Ah[1], Ah[2], Ah[3], b0p[0], b1p[0]);
    #pragma unroll
    for (int kt=1;kt<4;++kt){
      mma16816(acc[n], Ah[4*kt], Ah[4*kt+1], Ah[4*kt+2], Ah[4*kt+3], b0p[kt], b1p[kt]);
    }
  }
}

__global__ void __launch_bounds__(128,3) k_hmma(
   const float* __restrict__ Wcz, const float* __restrict__ bcz,
   const float* __restrict__ Wlz, const float* __restrict__ blz,
   const float* __restrict__ Wcr, const float* __restrict__ bcr,
   const float* __restrict__ Wlr, const float* __restrict__ blr,
   const float* __restrict__ Wch, const float* __restrict__ bch,
   const float* __restrict__ Wlh, const float* __restrict__ blh,
   float* __restrict__ out)
{
  extern __shared__ __align__(16) uint32_t sm[];
  float* smf = (float*)sm;

  int tid = threadIdx.x, lane = tid & 31, w = tid >> 5;
  int g = lane >> 2, tig = lane & 3;

  // ---- prologue: weights -> single bf16 fragment layout ----
  for (int idx = tid; idx < 128*32; idx += 128){
    int n = idx >> 5, p = idx & 31;
    int k0 = 2*p;
    float w0, w1;
    if (n < 64){ w0 = Wlz[(64+k0)*64 + n];  w1 = Wlz[(65+k0)*64 + n]; }
    else       { w0 = Wlr[(64+k0)*64 + n-64]; w1 = Wlr[(65+k0)*64 + n-64]; }
    sm[OFF_B1 + n*36 + qmap(p)] = bf2pack(w0, w1);
  }
  for (int idx = tid; idx < 64*32; idx += 128){
    int n = idx >> 5, p = idx & 31;
    int k0 = 2*p;
    sm[OFF_B2 + n*36 + qmap(p)] = bf2pack(Wlh[(64+k0)*64 + n], Wlh[(65+k0)*64 + n]);
  }
  for (int jj = tid; jj < 192; jj += 128){
    if (jj < 128){
      int j = jj & 63;
      const float* W  = (jj<64) ? Wlz : Wlr;
      const float* Wc = (jj<64) ? Wcz : Wcr;
      const float* bc = (jj<64) ? bcz : bcr;
      const float* bl = (jj<64) ? blz : blr;
      float u = 0.f, cc = 0.f;
      for (int k=0;k<64;++k){ float ww = W[k*64+j]; u = fmaf(Wc[k], ww, u); cc = fmaf(bc[k], ww, cc); }
      smf[OFF_UZR + jj] = u; smf[OFF_CZR + jj] = cc + bl[j];
    } else {
      int j = jj - 128;
      float u = 0.f, cc = 0.f;
      for (int k=0;k<64;++k){ float ww = Wlh[k*64+j]; u = fmaf(Wch[k], ww, u); cc = fmaf(bch[k], ww, cc); }
      smf[OFF_UH + j] = u; smf[OFF_CH + j] = cc + blh[j];
    }
  }
  int pbase = blockIdx.x*64;
  for (int idx = tid; idx < 64*20; idx += 128){
    int r = idx/20, t = idx - 20*r;
    int p = pbase + r; int b = p/NN, n = p - b*NN;
    smf[OFF_S + r*21 + t] = g_S[n*BT + b*TT + t];
  }
  __syncthreads();

  // warp-local rows
  int r0 = 16*w + g, r1 = r0 + 8;
  int P0 = pbase + r0, P1 = pbase + r1;
  int b0 = P0/NN, n0 = P0 - b0*NN;
  int b1 = P1/NN, n1 = P1 - b1*NN;
  float* out0 = out + ((size_t)(b0*TT)*NN + n0)*72 + 8 + 2*tig;
  float* out1 = out + ((size_t)(b1*TT)*NN + n1)*72 + 8 + 2*tig;
  const float* S0 = smf + OFF_S + r0*21;
  const float* S1 = smf + OFF_S + r1*21;

  const float2* uzr2 = (const float2*)(smf + OFF_UZR);
  const float2* czr2 = (const float2*)(smf + OFF_CZR);
  const float2* uh22 = (const float2*)(smf + OFF_UH);
  const float2* ch22 = (const float2*)(smf + OFF_CH);

  float h[8][4];
  uint32_t Ah[16];

  // ---- t = 0: H = 0, closed form ----
  {
    float s0 = S0[0], s1 = S1[0];
    #pragma unroll
    for (int n=0;n<8;++n){
      float2 uz = uzr2[4*n+tig], cz = czr2[4*n+tig];
      float2 uh = uh22[4*n+tig], ch = ch22[4*n+tig];
      #pragma unroll
      for (int j=0;j<4;++j){
        float s = (j<2) ? s0 : s1;
        float u  = (j&1) ? uz.y : uz.x;
        float c  = (j&1) ? cz.y : cz.x;
        float uu = (j&1) ? uh.y : uh.x;
        float cc = (j&1) ? ch.y : ch.x;
        float z  = sigm(fmaf(s, u, c));
        float ht = tanhap(fmaf(s, uu, cc));
        h[n][j] = (1.f - z)*ht;
      }
      *(float2*)(out0 + 8*n) = make_float2(h[n][0], h[n][1]);
      *(float2*)(out1 + 8*n) = make_float2(h[n][2], h[n][3]);
      int kt = n>>1, half = n&1;
      Ah[4*kt+2*half]   = bf2pack(h[n][0], h[n][1]);
      Ah[4*kt+2*half+1] = bf2pack(h[n][2], h[n][3]);
    }
    out0 += (size_t)NN*72;
    out1 += (size_t)NN*72;
  }

  for (int t=1; t<TT; ++t){
    float s0 = S0[t], s1 = S1[t];
    float acc[8][4];

    // ---- pass 1a: z (cols 0..63) ----
    mv_pass(sm + OFF_B1, Ah, acc, g, tig, 0);
    float z[8][4];
    #pragma unroll
    for (int n=0;n<8;++n){
      float2 uz = uzr2[4*n+tig], cz = czr2[4*n+tig];
      #pragma unroll
      for (int j=0;j<4;++j){
        float s = (j<2) ? s0 : s1;
        float u = (j&1) ? uz.y : uz.x;
        float c = (j&1) ? cz.y : cz.x;
        z[n][j] = sigm(acc[n][j] + fmaf(s, u, c));
      }
    }

    // ---- pass 1b: r (cols 64..127) -> HR packed straight into A frags ----
    mv_pass(sm + OFF_B1, Ah, acc, g, tig, 8);
    #pragma unroll
    for (int n=0;n<8;++n){
      float2 uz = uzr2[32 + 4*n+tig], cz = czr2[32 + 4*n+tig];
      float hr[4];
      #pragma unroll
      for (int j=0;j<4;++j){
        float s = (j<2) ? s0 : s1;
        float u = (j&1) ? uz.y : uz.x;
        float c = (j&1) ? cz.y : cz.x;
        float r = sigm(acc[n][j] + fmaf(s, u, c));
        hr[j] = h[n][j] * r;
      }
      int kt = n>>1, half = n&1;
      Ah[4*kt+2*half]   = bf2pack(hr[0], hr[1]);
      Ah[4*kt+2*half+1] = bf2pack(hr[2], hr[3]);
    }

    // ---- pass 2: htil = HR . Uh; blend; out; repack H ----
    mv_pass(sm + OFF_B2, Ah, acc, g, tig, 0);
    #pragma unroll
    for (int n=0;n<8;++n){
      float2 uh = uh22[4*n+tig], ch = ch22[4*n+tig];
      #pragma unroll
      for (int j=0;j<4;++j){
        float s = (j<2) ? s0 : s1;
        float u = (j&1) ? uh.y : uh.x;
        float c = (j&1) ? ch.y : ch.x;
        float ht = tanhap(acc[n][j] + fmaf(s, u, c));
        h[n][j] = fmaf(z[n][j], h[n][j] - ht, ht);
      }
      *(float2*)(out0 + 8*n) = make_float2(h[n][0], h[n][1]);
      *(float2*)(out1 + 8*n) = make_float2(h[n][2], h[n][3]);
      int kt = n>>1, half = n&1;
      Ah[4*kt+2*half]   = bf2pack(h[n][0], h[n][1]);
      Ah[4*kt+2*half+1] = bf2pack(h[n][2], h[n][3]);
    }
    out0 += (size_t)NN*72;
    out1 += (size_t)NN*72;
  }
}

extern "C" void kernel_launch(void* const* d_in, const int* in_sizes, int n_in,
                              void* d_out, int out_size) {
  const float* obs = (const float*)d_in[0];
  const int* ei32 = (const int*)d_in[1];
  int E = in_sizes[1] / 2;
  if (E > MAXE) E = MAXE;
  float* out = (float*)d_out;

  const int SMB = SM_WORDS*4;   // 34560 B
  cudaFuncSetAttribute(k_hmma, cudaFuncAttributeMaxDynamicSharedMemorySize, SMB);

  int obsBlocks = (BT*NN+255)/256;
  int cntBlocks = (E+255)/256;
  k_pre<<<(NN+255)/256, 256>>>(ei32);
  k_obs_count<<<obsBlocks+cntBlocks, 256>>>(obs, out, ei32, E, obsBlocks);
  k_scan<<<1, 256>>>();
  k_fill<<<cntBlocks, 256>>>(ei32, E);
  k_spmm<<<(NN*5*32+255)/256, 256>>>();
  k_hmma<<<(BB*NN)/64, 128, SMB>>>(
    (const float*)d_in[2], (const float*)d_in[3], (const float*)d_in[4], (const float*)d_in[5],
    (const float*)d_in[6], (const float*)d_in[7], (const float*)d_in[8], (const float*)d_in[9],
    (const float*)d_in[10], (const float*)d_in[11], (const float*)d_in[12], (const float*)d_in[13],
    out);
}